// round 11
// baseline (speedup 1.0000x reference)
#include <cuda_runtime.h>

#define Bn 8
#define Cn 64
#define Hn 128
#define Wn 128
#define On 64
#define KKn 9
#define HWn (Hn*Wn)

// Scratch: NHWC-transposed data and [k][c][o]-transposed weight.
__device__ float g_dT[Bn*HWn*Cn];     // 33.5 MB
__device__ float g_Wt[KKn*Cn*On];     // 147 KB

// ---------------- data transpose: NCHW -> NHWC ----------------
__global__ void transpose_data_k(const float* __restrict__ data) {
    __shared__ float tile[32][33];
    int b  = blockIdx.z;
    int c0 = blockIdx.y * 32;
    int p0 = blockIdx.x * 32;
    int tx = threadIdx.x, ty = threadIdx.y;
#pragma unroll
    for (int i = 0; i < 4; i++) {
        int c = c0 + ty + i * 8;
        tile[ty + i * 8][tx] = data[(b * Cn + c) * HWn + p0 + tx];
    }
    __syncthreads();
#pragma unroll
    for (int i = 0; i < 4; i++) {
        int p = p0 + ty + i * 8;
        g_dT[(b * HWn + p) * Cn + c0 + tx] = tile[tx][ty + i * 8];
    }
}

// ---------------- weight transpose: [o][c][k] -> [k][c][o] ----------------
__global__ void transpose_w_k(const float* __restrict__ w) {
    int i = blockIdx.x * 256 + threadIdx.x;
    if (i < On * Cn * KKn) {
        int k = i % KKn;
        int c = (i / KKn) % Cn;
        int o = i / (KKn * Cn);
        g_Wt[(k * Cn + c) * On + o] = w[i];
    }
}

// ---------------- main kernel ----------------
// Block: (b, 2 output rows) = 256 pixels. 256 threads.
// smem: sW2[64c][64o] duplicated-pair weights (32KB) + sS[64c][256pix swizzled] (64KB)
//       + per-pixel corner weights (4KB) + corner offsets (4KB) = 106496 B.

// Packed dual-fp32 FMA: acc{2 floats} += a{2 floats} * w{2 floats} (elementwise)
#define FMA2(acc, av, wv) \
    asm("fma.rn.f32x2 %0, %1, %2, %0;" : "+l"(acc) : "l"(av), "l"(wv))

__device__ __forceinline__ unsigned long long dup_f32(float w) {
    unsigned int b = __float_as_uint(w);
    return ((unsigned long long)b << 32) | (unsigned long long)b;
}

__global__ void __launch_bounds__(256, 2)
deform_main_k(const float* __restrict__ offset, float* __restrict__ out) {
    extern __shared__ float smem[];
    unsigned long long* sW2 = (unsigned long long*)smem;       // 8192 floats worth (32KB)
    float* sS  = smem + 8192;                                  // 16384 floats
    float* sWt = smem + 8192 + 16384;                          // 1024 floats (float4/pixel)
    int*   sOf = (int*)(smem + 8192 + 16384 + 1024);           // 1024 ints (int4/pixel)

    int b  = blockIdx.y;
    int h0 = blockIdx.x * 2;
    int tid = threadIdx.x;
    int tx = tid & 31, ty = tid >> 5;

    const float* dB = g_dT + (size_t)b * HWn * Cn;

    // acc[o][pixpair]: 8 o-values x 2 pixel-pairs, for each of 2 rows (A,B).
    unsigned long long accA[8][2], accB[8][2];
#pragma unroll
    for (int i = 0; i < 8; i++) {
        accA[i][0] = accA[i][1] = 0ull;   // bit pattern of {0.f,0.f}
        accB[i][0] = accB[i][1] = 0ull;
    }

#pragma unroll 1
    for (int kk = 0; kk < KKn; kk++) {
        __syncthreads();  // protect smem from previous iteration's readers

        // ---- per-pixel sampling params (one pixel per thread) ----
        {
            int p  = tid;
            int hh = h0 + (p >> 7);
            int ww = p & 127;
            const float* ob = offset + (((size_t)b * 18 + 2 * kk) * Hn + hh) * Wn + ww;
            float oy = ob[0];
            float ox = ob[HWn];
            int ki = kk / 3, kj = kk - ki * 3;
            float py = oy + (float)(hh - 1 + ki);
            float px = ox + (float)(ww - 1 + kj);
            float fy = floorf(py), fx = floorf(px);
            float ly = py - fy,  lx = px - fx;
            int y0 = (int)fy, x0 = (int)fx;
            int y1 = y0 + 1, x1 = x0 + 1;
            float vy0 = (y0 >= 0 && y0 < Hn) ? 1.f : 0.f;
            float vy1 = (y1 >= 0 && y1 < Hn) ? 1.f : 0.f;
            float vx0 = (x0 >= 0 && x0 < Wn) ? 1.f : 0.f;
            float vx1 = (x1 >= 0 && x1 < Wn) ? 1.f : 0.f;
            int cy0 = max(0, min(Hn - 1, y0)), cy1 = max(0, min(Hn - 1, y1));
            int cx0 = max(0, min(Wn - 1, x0)), cx1 = max(0, min(Wn - 1, x1));
            float w00 = (1.f - ly) * (1.f - lx) * vy0 * vx0;
            float w01 = (1.f - ly) * lx         * vy0 * vx1;
            float w10 = ly         * (1.f - lx) * vy1 * vx0;
            float w11 = ly         * lx         * vy1 * vx1;
            ((int4*)sOf)[p] = make_int4((cy0 * Wn + cx0) * Cn, (cy0 * Wn + cx1) * Cn,
                                        (cy1 * Wn + cx0) * Cn, (cy1 * Wn + cx1) * Cn);
            ((float4*)sWt)[p] = make_float4(w00, w01, w10, w11);
        }

        // ---- stage weight tile for this k, duplicated pairs: sW2[c*64+o] = {w,w} ----
        {
            const float4* src = (const float4*)(g_Wt + kk * Cn * On);
            ulonglong2* dst = (ulonglong2*)sW2;
#pragma unroll
            for (int r = 0; r < 4; r++) {
                int idx = tid + 256 * r;           // float4 index; covers 4 o-values
                float4 v = src[idx];
                dst[idx * 2 + 0] = make_ulonglong2(dup_f32(v.x), dup_f32(v.y));
                dst[idx * 2 + 1] = make_ulonglong2(dup_f32(v.z), dup_f32(v.w));
            }
        }
        __syncthreads();

        // ---- sampling: NHWC float4 gathers, swizzled STS into sS[c][pix] ----
        {
            int cg = tid & 15;       // channel group: c = 4*cg .. 4*cg+3
            int pl = tid >> 4;       // pixel lane
            const float* dC = dB + cg * 4;
#pragma unroll
            for (int it = 0; it < 16; it++) {
                int p = pl + it * 16;
                int4   a  = ((int4*)sOf)[p];
                float4 wv = ((float4*)sWt)[p];
                float4 v00 = *(const float4*)(dC + a.x);
                float4 v01 = *(const float4*)(dC + a.y);
                float4 v10 = *(const float4*)(dC + a.z);
                float4 v11 = *(const float4*)(dC + a.w);
                float4 s;
                s.x = wv.x * v00.x + wv.y * v01.x + wv.z * v10.x + wv.w * v11.x;
                s.y = wv.x * v00.y + wv.y * v01.y + wv.z * v10.y + wv.w * v11.y;
                s.z = wv.x * v00.z + wv.y * v01.z + wv.z * v10.z + wv.w * v11.z;
                s.w = wv.x * v00.w + wv.y * v01.w + wv.z * v10.w + wv.w * v11.w;
                // XOR swizzle on 16B groups: col4 = (pix>>2) ^ ((c>>2)&7); (c>>2)&7 == cg&7
                int col = 4 * ((p >> 2) ^ (cg & 7)) + (p & 3);
                float* ss = sS + (cg * 4) * 256 + col;
                ss[0]   = s.x;
                ss[256] = s.y;
                ss[512] = s.z;
                ss[768] = s.w;
            }
        }
        __syncthreads();

        // ---- GEMM (packed f32x2): acc[o=8][pix=8] += W[c][o] * S[c][pix] ----
        {
            const ulonglong2* uS = (const ulonglong2*)sS;   // 2 pixel-pairs per elem
            const ulonglong2* uW = (const ulonglong2*)sW2;  // 2 dup-weights per elem
#pragma unroll 2
            for (int c = 0; c < 64; c++) {
                int sw = (c >> 2) & 7;
                ulonglong2 a  = uS[c * 64 + (tx ^ sw)];       // pixels 4tx..4tx+3 (row h0)
                ulonglong2 bb = uS[c * 64 + 32 + (tx ^ sw)];  // row h0+1
                // 8 dup-weights for o = 8ty..8ty+7 (warp-broadcast LDS)
                ulonglong2 w01 = uW[c * 32 + ty * 4 + 0];
                ulonglong2 w23 = uW[c * 32 + ty * 4 + 1];
                ulonglong2 w45 = uW[c * 32 + ty * 4 + 2];
                ulonglong2 w67 = uW[c * 32 + ty * 4 + 3];
                FMA2(accA[0][0], a.x, w01.x); FMA2(accA[0][1], a.y, w01.x);
                FMA2(accB[0][0], bb.x, w01.x); FMA2(accB[0][1], bb.y, w01.x);
                FMA2(accA[1][0], a.x, w01.y); FMA2(accA[1][1], a.y, w01.y);
                FMA2(accB[1][0], bb.x, w01.y); FMA2(accB[1][1], bb.y, w01.y);
                FMA2(accA[2][0], a.x, w23.x); FMA2(accA[2][1], a.y, w23.x);
                FMA2(accB[2][0], bb.x, w23.x); FMA2(accB[2][1], bb.y, w23.x);
                FMA2(accA[3][0], a.x, w23.y); FMA2(accA[3][1], a.y, w23.y);
                FMA2(accB[3][0], bb.x, w23.y); FMA2(accB[3][1], bb.y, w23.y);
                FMA2(accA[4][0], a.x, w45.x); FMA2(accA[4][1], a.y, w45.x);
                FMA2(accB[4][0], bb.x, w45.x); FMA2(accB[4][1], bb.y, w45.x);
                FMA2(accA[5][0], a.x, w45.y); FMA2(accA[5][1], a.y, w45.y);
                FMA2(accB[5][0], bb.x, w45.y); FMA2(accB[5][1], bb.y, w45.y);
                FMA2(accA[6][0], a.x, w67.x); FMA2(accA[6][1], a.y, w67.x);
                FMA2(accB[6][0], bb.x, w67.x); FMA2(accB[6][1], bb.y, w67.x);
                FMA2(accA[7][0], a.x, w67.y); FMA2(accA[7][1], a.y, w67.y);
                FMA2(accB[7][0], bb.x, w67.y); FMA2(accB[7][1], bb.y, w67.y);
            }
        }
    }

    // ---- epilogue: out[b][o][h][w], coalesced 16B stores ----
#pragma unroll
    for (int i = 0; i < 8; i++) {
        int o = ty * 8 + i;
        float* op = out + (((size_t)b * On + o) * Hn + h0) * Wn;
        ((ulonglong2*)op)[tx]        = make_ulonglong2(accA[i][0], accA[i][1]);  // row h0
        ((ulonglong2*)(op + Wn))[tx] = make_ulonglong2(accB[i][0], accB[i][1]);  // row h0+1
    }
}

extern "C" void kernel_launch(void* const* d_in, const int* in_sizes, int n_in,
                              void* d_out, int out_size) {
    const float* data   = (const float*)d_in[0];
    const float* offset = (const float*)d_in[1];
    const float* weight = (const float*)d_in[2];
    float* out = (float*)d_out;

    transpose_data_k<<<dim3(HWn / 32, Cn / 32, Bn), dim3(32, 8)>>>(data);
    transpose_w_k<<<(KKn * Cn * On + 255) / 256, 256>>>(weight);

    cudaFuncSetAttribute(deform_main_k,
                         cudaFuncAttributeMaxDynamicSharedMemorySize, 106496);
    deform_main_k<<<dim3(Hn / 2, Bn), 256, 106496>>>(offset, out);
}

// round 13
// speedup vs baseline: 1.9232x; 1.9232x over previous
#include <cuda_runtime.h>
#include <cuda_bf16.h>

#define Bn 8
#define Cn 64
#define Hn 128
#define Wn 128
#define On 64
#define KKn 9
#define HWn (Hn*Wn)

// Scratch: NHWC-transposed data + bf16-split weights [k][c][o].
__device__ float g_dT[Bn*HWn*Cn];                  // 33.5 MB
__device__ __nv_bfloat16 g_Whi[KKn*Cn*On];         // 72 KB
__device__ __nv_bfloat16 g_Wlo[KKn*Cn*On];         // 72 KB

__device__ __forceinline__ unsigned smem_u32(const void* p) {
    unsigned a;
    asm("{ .reg .u64 t; cvta.to.shared.u64 t, %1; cvt.u32.u64 %0, t; }" : "=r"(a) : "l"(p));
    return a;
}
__device__ __forceinline__ void ldsm_x4(unsigned* r, unsigned addr) {
    asm volatile("ldmatrix.sync.aligned.m8n8.x4.shared.b16 {%0,%1,%2,%3}, [%4];"
        : "=r"(r[0]), "=r"(r[1]), "=r"(r[2]), "=r"(r[3]) : "r"(addr));
}
__device__ __forceinline__ void ldsm_x2t(unsigned* r, unsigned addr) {
    asm volatile("ldmatrix.sync.aligned.m8n8.x2.trans.shared.b16 {%0,%1}, [%2];"
        : "=r"(r[0]), "=r"(r[1]) : "r"(addr));
}
__device__ __forceinline__ void mma_bf16(float* d, const unsigned* a, const unsigned* b) {
    asm volatile("mma.sync.aligned.m16n8k16.row.col.f32.bf16.bf16.f32 "
        "{%0,%1,%2,%3}, {%4,%5,%6,%7}, {%8,%9}, {%0,%1,%2,%3};"
        : "+f"(d[0]), "+f"(d[1]), "+f"(d[2]), "+f"(d[3])
        : "r"(a[0]), "r"(a[1]), "r"(a[2]), "r"(a[3]), "r"(b[0]), "r"(b[1]));
}
#define SWZ(off) ((off) ^ (((off) >> 3) & 0x70))

// ---------------- data transpose: NCHW -> NHWC ----------------
__global__ void transpose_data_k(const float* __restrict__ data) {
    __shared__ float tile[32][33];
    int b  = blockIdx.z;
    int c0 = blockIdx.y * 32;
    int p0 = blockIdx.x * 32;
    int tx = threadIdx.x, ty = threadIdx.y;
#pragma unroll
    for (int i = 0; i < 4; i++) {
        int c = c0 + ty + i * 8;
        tile[ty + i * 8][tx] = data[(b * Cn + c) * HWn + p0 + tx];
    }
    __syncthreads();
#pragma unroll
    for (int i = 0; i < 4; i++) {
        int p = p0 + ty + i * 8;
        g_dT[(b * HWn + p) * Cn + c0 + tx] = tile[tx][ty + i * 8];
    }
}

// ---------------- weight prep: [o][c][k] fp32 -> bf16 hi/lo [k][c][o] ----------------
__global__ void prep_w_k(const float* __restrict__ w) {
    int i = blockIdx.x * 256 + threadIdx.x;
    if (i < KKn * Cn * On) {
        int k = i >> 12;                 // i = k*4096 + c*64 + o
        int c = (i >> 6) & 63;
        int o = i & 63;
        float v = w[(o * Cn + c) * KKn + k];
        __nv_bfloat16 hi = __float2bfloat16(v);
        __nv_bfloat16 lo = __float2bfloat16(v - __bfloat162float(hi));
        g_Whi[i] = hi;
        g_Wlo[i] = lo;
    }
}

// ---------------- main kernel ----------------
// Block = (b, 2 output rows) = 256 pixels, 512 threads, 1 CTA/SM.
// smem: A_hi@0 (32KB, [256pix][64c] bf16 swizzled), A_lo@32768 (32KB),
//       W_hi@65536 (8KB, [64c][64o] bf16 swizzled), W_lo@73728 (8KB),
//       bilin wts@81920 (4KB), corner offs@86016 (4KB). Total 90112.
// Epilogue reuses smem base as float D[64o][264pix-padded] (67.6KB).
#define SM_AHI  0
#define SM_ALO  32768
#define SM_WHI  65536
#define SM_WLO  73728
#define SM_WT   81920
#define SM_OF   86016
#define SMEM_TOTAL 90112

__global__ void __launch_bounds__(512, 1)
deform_main_k(const float* __restrict__ offset, float* __restrict__ out) {
    extern __shared__ char smem[];
    unsigned sb = smem_u32(smem);
    int tid = threadIdx.x, wid = tid >> 5, lane = tid & 31;
    int b = blockIdx.y, h0 = blockIdx.x * 2;

    float* sWt = (float*)(smem + SM_WT);
    int*   sOf = (int*)(smem + SM_OF);
    const float* dB = g_dT + (size_t)b * HWn * Cn;

    float acc[8][4];
#pragma unroll
    for (int j = 0; j < 8; j++)
#pragma unroll
        for (int r = 0; r < 4; r++) acc[j][r] = 0.f;

    // ldmatrix source addresses (within-warp constants)
    int g = lane >> 2, tig = lane & 3;
    unsigned aRow = (unsigned)(wid * 16 + (lane & 15)) * 128 + ((lane >> 4) & 1) * 16;
    // B row for x2.trans: lanes 0-15 supply addresses
    unsigned bRowLane = (unsigned)(lane & 15) * 128;

#pragma unroll 1
    for (int kk = 0; kk < KKn; kk++) {
        __syncthreads();  // previous GEMM done reading smem

        // ---- per-pixel sampling params (pixels 0..255, one per thread) ----
        if (tid < 256) {
            int p  = tid;
            int hh = h0 + (p >> 7);
            int ww = p & 127;
            const float* ob = offset + (((size_t)b * 18 + 2 * kk) * Hn + hh) * Wn + ww;
            float oy = ob[0];
            float ox = ob[HWn];
            int ki = kk / 3, kj = kk - ki * 3;
            float py = oy + (float)(hh - 1 + ki);
            float px = ox + (float)(ww - 1 + kj);
            float fy = floorf(py), fx = floorf(px);
            float ly = py - fy, lx = px - fx;
            int y0 = (int)fy, x0 = (int)fx;
            int y1 = y0 + 1, x1 = x0 + 1;
            float vy0 = (y0 >= 0 && y0 < Hn) ? 1.f : 0.f;
            float vy1 = (y1 >= 0 && y1 < Hn) ? 1.f : 0.f;
            float vx0 = (x0 >= 0 && x0 < Wn) ? 1.f : 0.f;
            float vx1 = (x1 >= 0 && x1 < Wn) ? 1.f : 0.f;
            int cy0 = max(0, min(Hn - 1, y0)), cy1 = max(0, min(Hn - 1, y1));
            int cx0 = max(0, min(Wn - 1, x0)), cx1 = max(0, min(Wn - 1, x1));
            float w00 = (1.f - ly) * (1.f - lx) * vy0 * vx0;
            float w01 = (1.f - ly) * lx         * vy0 * vx1;
            float w10 = ly         * (1.f - lx) * vy1 * vx0;
            float w11 = ly         * lx         * vy1 * vx1;
            ((int4*)sOf)[p] = make_int4((cy0 * Wn + cx0) * Cn, (cy0 * Wn + cx1) * Cn,
                                        (cy1 * Wn + cx0) * Cn, (cy1 * Wn + cx1) * Cn);
            ((float4*)sWt)[p] = make_float4(w00, w01, w10, w11);
        }

        // ---- stage bf16 W tiles [64c][64o] for this kk, SW128-swizzled ----
        {
            const uint4* srcH = (const uint4*)((const char*)g_Whi + kk * 8192);
            const uint4* srcL = (const uint4*)((const char*)g_Wlo + kk * 8192);
            unsigned sw = SWZ((unsigned)(tid * 16));
            *(uint4*)(smem + SM_WHI + sw) = srcH[tid];
            *(uint4*)(smem + SM_WLO + sw) = srcL[tid];
        }
        __syncthreads();

        // ---- sampling: NHWC float4 gathers -> bf16 hi/lo split -> swizzled STS ----
        {
            int cg = tid & 15;       // channel group: c = 4cg..4cg+3
            int pl = tid >> 4;       // 0..31
            const float* dC = dB + cg * 4;
#pragma unroll
            for (int it = 0; it < 8; it++) {
                int p = pl + it * 32;
                int4   a  = ((int4*)sOf)[p];
                float4 wv = ((float4*)sWt)[p];
                float4 v00 = *(const float4*)(dC + a.x);
                float4 v01 = *(const float4*)(dC + a.y);
                float4 v10 = *(const float4*)(dC + a.z);
                float4 v11 = *(const float4*)(dC + a.w);
                float4 s;
                s.x = wv.x * v00.x + wv.y * v01.x + wv.z * v10.x + wv.w * v11.x;
                s.y = wv.x * v00.y + wv.y * v01.y + wv.z * v10.y + wv.w * v11.y;
                s.z = wv.x * v00.z + wv.y * v01.z + wv.z * v10.z + wv.w * v11.z;
                s.w = wv.x * v00.w + wv.y * v01.w + wv.z * v10.w + wv.w * v11.w;
                __nv_bfloat162 h01 = __floats2bfloat162_rn(s.x, s.y);
                __nv_bfloat162 h23 = __floats2bfloat162_rn(s.z, s.w);
                float2 f01 = __bfloat1622float2(h01);
                float2 f23 = __bfloat1622float2(h23);
                __nv_bfloat162 l01 = __floats2bfloat162_rn(s.x - f01.x, s.y - f01.y);
                __nv_bfloat162 l23 = __floats2bfloat162_rn(s.z - f23.x, s.w - f23.y);
                unsigned sw = SWZ((unsigned)(p * 128 + cg * 8));
                *(uint2*)(smem + SM_AHI + sw) =
                    make_uint2(*(unsigned*)&h01, *(unsigned*)&h23);
                *(uint2*)(smem + SM_ALO + sw) =
                    make_uint2(*(unsigned*)&l01, *(unsigned*)&l23);
            }
        }
        __syncthreads();

        // ---- GEMM via mma.sync bf16: acc[pix16 x o64] += 3 split terms ----
        {
            unsigned af[4], bf[8][2];
#pragma unroll
            for (int ks = 0; ks < 4; ks++) {
                unsigned aOff = SWZ(aRow + ks * 32);
                unsigned bRow = SWZ(bRowLane + ks * 2048);  // +16 c-rows = 2048B
#pragma unroll
                for (int j = 0; j < 8; j++)
                    ldsm_x2t(bf[j], sb + SM_WHI + SWZ(bRowLane + ks * 2048 + j * 16));
                ldsm_x4(af, sb + SM_AHI + aOff);
#pragma unroll
                for (int j = 0; j < 8; j++) mma_bf16(acc[j], af, bf[j]);
                ldsm_x4(af, sb + SM_ALO + aOff);
#pragma unroll
                for (int j = 0; j < 8; j++) mma_bf16(acc[j], af, bf[j]);
                (void)bRow;
            }
#pragma unroll
            for (int ks = 0; ks < 4; ks++) {
                unsigned aOff = SWZ(aRow + ks * 32);
#pragma unroll
                for (int j = 0; j < 8; j++)
                    ldsm_x2t(bf[j], sb + SM_WLO + SWZ(bRowLane + ks * 2048 + j * 16));
                ldsm_x4(af, sb + SM_AHI + aOff);
#pragma unroll
                for (int j = 0; j < 8; j++) mma_bf16(acc[j], af, bf[j]);
            }
        }
    }

    // ---- epilogue: fragments -> smem [64o][264] -> coalesced stores ----
    __syncthreads();   // last GEMM reads done; reuse smem
    {
        float* sD = (float*)smem;
        int pixA = wid * 16 + g;       // regs 0,1
        int pixB = pixA + 8;           // regs 2,3
#pragma unroll
        for (int j = 0; j < 8; j++) {
            int o = j * 8 + tig * 2;
            sD[o * 264 + pixA]       = acc[j][0];
            sD[(o + 1) * 264 + pixA] = acc[j][1];
            sD[o * 264 + pixB]       = acc[j][2];
            sD[(o + 1) * 264 + pixB] = acc[j][3];
        }
    }
    __syncthreads();
    {
        const float* sD = (const float*)smem;
#pragma unroll
        for (int r = 0; r < 8; r++) {
            int idx = tid + r * 512;       // 4096 float4 rows total
            int o = idx >> 6;
            int seg = idx & 63;
            int pix = seg * 4;
            int h = h0 + (pix >> 7);
            int w_ = pix & 127;
            const float* s = sD + o * 264 + pix;
            float4 v = make_float4(s[0], s[1], s[2], s[3]);
            *(float4*)(out + ((size_t)b * On + o) * HWn + (size_t)h * Wn + w_) = v;
        }
    }
}

extern "C" void kernel_launch(void* const* d_in, const int* in_sizes, int n_in,
                              void* d_out, int out_size) {
    const float* data   = (const float*)d_in[0];
    const float* offset = (const float*)d_in[1];
    const float* weight = (const float*)d_in[2];
    float* out = (float*)d_out;

    transpose_data_k<<<dim3(HWn / 32, Cn / 32, Bn), dim3(32, 8)>>>(data);
    prep_w_k<<<(KKn * Cn * On + 255) / 256, 256>>>(weight);

    cudaFuncSetAttribute(deform_main_k,
                         cudaFuncAttributeMaxDynamicSharedMemorySize, SMEM_TOTAL);
    deform_main_k<<<dim3(Hn / 2, Bn), 512, SMEM_TOTAL>>>(offset, out);
}

// round 16
// speedup vs baseline: 2.0402x; 1.0608x over previous
#include <cuda_runtime.h>
#include <cuda_bf16.h>

#define Bn 8
#define Cn 64
#define Hn 128
#define Wn 128
#define On 64
#define KKn 9
#define HWn (Hn*Wn)

// Scratch: NHWC-transposed data + bf16-split weights [k][c][o].
__device__ float g_dT[Bn*HWn*Cn];                  // 33.5 MB
__device__ __nv_bfloat16 g_Whi[KKn*Cn*On];         // 72 KB
__device__ __nv_bfloat16 g_Wlo[KKn*Cn*On];         // 72 KB

__device__ __forceinline__ unsigned smem_u32(const void* p) {
    unsigned a;
    asm("{ .reg .u64 t; cvta.to.shared.u64 t, %1; cvt.u32.u64 %0, t; }" : "=r"(a) : "l"(p));
    return a;
}
__device__ __forceinline__ void ldsm_x4(unsigned* r, unsigned addr) {
    asm volatile("ldmatrix.sync.aligned.m8n8.x4.shared.b16 {%0,%1,%2,%3}, [%4];"
        : "=r"(r[0]), "=r"(r[1]), "=r"(r[2]), "=r"(r[3]) : "r"(addr));
}
__device__ __forceinline__ void ldsm_x2t(unsigned* r, unsigned addr) {
    asm volatile("ldmatrix.sync.aligned.m8n8.x2.trans.shared.b16 {%0,%1}, [%2];"
        : "=r"(r[0]), "=r"(r[1]) : "r"(addr));
}
__device__ __forceinline__ void mma_bf16(float* d, const unsigned* a, const unsigned* b) {
    asm volatile("mma.sync.aligned.m16n8k16.row.col.f32.bf16.bf16.f32 "
        "{%0,%1,%2,%3}, {%4,%5,%6,%7}, {%8,%9}, {%0,%1,%2,%3};"
        : "+f"(d[0]), "+f"(d[1]), "+f"(d[2]), "+f"(d[3])
        : "r"(a[0]), "r"(a[1]), "r"(a[2]), "r"(a[3]), "r"(b[0]), "r"(b[1]));
}
#define SWZ(off) ((off) ^ (((off) >> 3) & 0x70))

// ---------------- data transpose: NCHW -> NHWC ----------------
__global__ void transpose_data_k(const float* __restrict__ data) {
    __shared__ float tile[32][33];
    int b  = blockIdx.z;
    int c0 = blockIdx.y * 32;
    int p0 = blockIdx.x * 32;
    int tx = threadIdx.x, ty = threadIdx.y;
#pragma unroll
    for (int i = 0; i < 4; i++) {
        int c = c0 + ty + i * 8;
        tile[ty + i * 8][tx] = data[(b * Cn + c) * HWn + p0 + tx];
    }
    __syncthreads();
#pragma unroll
    for (int i = 0; i < 4; i++) {
        int p = p0 + ty + i * 8;
        g_dT[(b * HWn + p) * Cn + c0 + tx] = tile[tx][ty + i * 8];
    }
}

// ---------------- weight prep: [o][c][k] fp32 -> bf16 hi/lo [k][c][o] ----------------
__global__ void prep_w_k(const float* __restrict__ w) {
    int i = blockIdx.x * 256 + threadIdx.x;
    if (i < KKn * Cn * On) {
        int k = i >> 12;                 // i = k*4096 + c*64 + o
        int c = (i >> 6) & 63;
        int o = i & 63;
        float v = w[(o * Cn + c) * KKn + k];
        __nv_bfloat16 hi = __float2bfloat16(v);
        __nv_bfloat16 lo = __float2bfloat16(v - __bfloat162float(hi));
        g_Whi[i] = hi;
        g_Wlo[i] = lo;
    }
}

// ---------------- main kernel ----------------
// Block = (b, 2 output rows) = 256 pixels, 512 threads, 1 CTA/SM.
// Software-pipelined: gather(kk) + params(kk+1) + stageW(kk+1) + gemm(kk-1)
// share ONE inter-barrier region. A double-buffered, W triple-buffered,
// params double-buffered. smem total 196608 B (192KB).
// Epilogue reuses smem base as float D[64o][264pix-padded] (67.6KB).
#define SMEM_TOTAL 196608

__global__ void __launch_bounds__(512, 1)
deform_main_k(const float* __restrict__ offset, float* __restrict__ out) {
    extern __shared__ char smem[];
    unsigned sb = smem_u32(smem);
    int tid = threadIdx.x, wid = tid >> 5, lane = tid & 31;
    int b = blockIdx.y, h0 = blockIdx.x * 2;

    const unsigned AH[2] = {0u, 65536u};
    const unsigned AL[2] = {32768u, 98304u};
    const unsigned WH[3] = {131072u, 147456u, 163840u};
    const unsigned WL[3] = {139264u, 155648u, 172032u};
    const unsigned PW[2] = {180224u, 188416u};
    const unsigned PO[2] = {184320u, 192512u};

    const float* dB = g_dT + (size_t)b * HWn * Cn;

    float acc[8][4];
#pragma unroll
    for (int j = 0; j < 8; j++)
#pragma unroll
        for (int r = 0; r < 4; r++) acc[j][r] = 0.f;

    int g = lane >> 2, tig = lane & 3;
    unsigned aRow = (unsigned)(wid * 16 + (lane & 15)) * 128 + ((lane >> 4) & 1) * 16;
    unsigned bRowLane = (unsigned)(lane & 15) * 128;

    // ---- helpers as lambdas ----
    auto params_phase = [&](int kk, int pb) {
        if (tid < 256) {
            int p  = tid;
            int hh = h0 + (p >> 7);
            int ww = p & 127;
            const float* ob = offset + (((size_t)b * 18 + 2 * kk) * Hn + hh) * Wn + ww;
            float oy = ob[0];
            float ox = ob[HWn];
            int ki = kk / 3, kj = kk - ki * 3;
            float py = oy + (float)(hh - 1 + ki);
            float px = ox + (float)(ww - 1 + kj);
            float fy = floorf(py), fx = floorf(px);
            float ly = py - fy, lx = px - fx;
            int y0 = (int)fy, x0 = (int)fx;
            int y1 = y0 + 1, x1 = x0 + 1;
            float vy0 = (y0 >= 0 && y0 < Hn) ? 1.f : 0.f;
            float vy1 = (y1 >= 0 && y1 < Hn) ? 1.f : 0.f;
            float vx0 = (x0 >= 0 && x0 < Wn) ? 1.f : 0.f;
            float vx1 = (x1 >= 0 && x1 < Wn) ? 1.f : 0.f;
            int cy0 = max(0, min(Hn - 1, y0)), cy1 = max(0, min(Hn - 1, y1));
            int cx0 = max(0, min(Wn - 1, x0)), cx1 = max(0, min(Wn - 1, x1));
            float w00 = (1.f - ly) * (1.f - lx) * vy0 * vx0;
            float w01 = (1.f - ly) * lx         * vy0 * vx1;
            float w10 = ly         * (1.f - lx) * vy1 * vx0;
            float w11 = ly         * lx         * vy1 * vx1;
            ((int4*)(smem + PO[pb]))[p] =
                make_int4((cy0 * Wn + cx0) * Cn, (cy0 * Wn + cx1) * Cn,
                          (cy1 * Wn + cx0) * Cn, (cy1 * Wn + cx1) * Cn);
            ((float4*)(smem + PW[pb]))[p] = make_float4(w00, w01, w10, w11);
        }
    };
    auto stage_w = [&](int kk, int wb) {
        const uint4* srcH = (const uint4*)((const char*)g_Whi + kk * 8192);
        const uint4* srcL = (const uint4*)((const char*)g_Wlo + kk * 8192);
        unsigned sw = SWZ((unsigned)(tid * 16));
        *(uint4*)(smem + WH[wb] + sw) = srcH[tid];
        *(uint4*)(smem + WL[wb] + sw) = srcL[tid];
    };
    auto gather_phase = [&](int ab, int pb) {
        int cg = tid & 15;
        int pl = tid >> 4;       // 0..31
        const float* dC = dB + cg * 4;
        const int4*   of = (const int4*)(smem + PO[pb]);
        const float4* wt = (const float4*)(smem + PW[pb]);
#pragma unroll
        for (int it = 0; it < 8; it++) {
            int p = pl + it * 32;
            int4   a  = of[p];
            float4 wv = wt[p];
            float4 v00 = *(const float4*)(dC + a.x);
            float4 v01 = *(const float4*)(dC + a.y);
            float4 v10 = *(const float4*)(dC + a.z);
            float4 v11 = *(const float4*)(dC + a.w);
            float4 s;
            s.x = wv.x * v00.x + wv.y * v01.x + wv.z * v10.x + wv.w * v11.x;
            s.y = wv.x * v00.y + wv.y * v01.y + wv.z * v10.y + wv.w * v11.y;
            s.z = wv.x * v00.z + wv.y * v01.z + wv.z * v10.z + wv.w * v11.z;
            s.w = wv.x * v00.w + wv.y * v01.w + wv.z * v10.w + wv.w * v11.w;
            __nv_bfloat162 h01 = __floats2bfloat162_rn(s.x, s.y);
            __nv_bfloat162 h23 = __floats2bfloat162_rn(s.z, s.w);
            float2 f01 = __bfloat1622float2(h01);
            float2 f23 = __bfloat1622float2(h23);
            __nv_bfloat162 l01 = __floats2bfloat162_rn(s.x - f01.x, s.y - f01.y);
            __nv_bfloat162 l23 = __floats2bfloat162_rn(s.z - f23.x, s.w - f23.y);
            unsigned sw = SWZ((unsigned)(p * 128 + cg * 8));
            *(uint2*)(smem + AH[ab] + sw) = make_uint2(*(unsigned*)&h01, *(unsigned*)&h23);
            *(uint2*)(smem + AL[ab] + sw) = make_uint2(*(unsigned*)&l01, *(unsigned*)&l23);
        }
    };
    auto gemm_phase = [&](int ab, int wb) {
        unsigned af[4], bf[8][2];
#pragma unroll
        for (int ks = 0; ks < 4; ks++) {
            unsigned aOff = SWZ(aRow + ks * 32);
#pragma unroll
            for (int j = 0; j < 8; j++)
                ldsm_x2t(bf[j], sb + WH[wb] + SWZ(bRowLane + ks * 2048 + j * 16));
            ldsm_x4(af, sb + AH[ab] + aOff);
#pragma unroll
            for (int j = 0; j < 8; j++) mma_bf16(acc[j], af, bf[j]);
            ldsm_x4(af, sb + AL[ab] + aOff);
#pragma unroll
            for (int j = 0; j < 8; j++) mma_bf16(acc[j], af, bf[j]);
        }
#pragma unroll
        for (int ks = 0; ks < 4; ks++) {
            unsigned aOff = SWZ(aRow + ks * 32);
#pragma unroll
            for (int j = 0; j < 8; j++)
                ldsm_x2t(bf[j], sb + WL[wb] + SWZ(bRowLane + ks * 2048 + j * 16));
            ldsm_x4(af, sb + AH[ab] + aOff);
#pragma unroll
            for (int j = 0; j < 8; j++) mma_bf16(acc[j], af, bf[j]);
        }
    };

    // ---- prologue: params(0), W(0) ----
    params_phase(0, 0);
    stage_w(0, 0);
    __syncthreads();

    // ---- pipelined main loop ----
#pragma unroll 1
    for (int kk = 0; kk < KKn; kk++) {
        int cb = kk & 1;
        gather_phase(cb, cb);                 // gather(kk) into A[cb] using P[cb]
        if (kk + 1 < KKn) {
            params_phase(kk + 1, cb ^ 1);     // params(kk+1) -> P[cb^1]
            stage_w(kk + 1, (kk + 1) % 3);    // W(kk+1) -> W[(kk+1)%3]
        }
        if (kk > 0)
            gemm_phase((kk - 1) & 1, (kk - 1) % 3);  // gemm(kk-1)
        __syncthreads();
    }
    gemm_phase((KKn - 1) & 1, (KKn - 1) % 3);        // gemm(8)

    // ---- epilogue: fragments -> smem [64o][264] -> coalesced stores ----
    __syncthreads();   // all GEMM reads done; reuse smem
    {
        float* sD = (float*)smem;
        int pixA = wid * 16 + g;       // regs 0,1
        int pixB = pixA + 8;           // regs 2,3
#pragma unroll
        for (int j = 0; j < 8; j++) {
            int o = j * 8 + tig * 2;
            sD[o * 264 + pixA]       = acc[j][0];
            sD[(o + 1) * 264 + pixA] = acc[j][1];
            sD[o * 264 + pixB]       = acc[j][2];
            sD[(o + 1) * 264 + pixB] = acc[j][3];
        }
    }
    __syncthreads();
    {
        const float* sD = (const float*)smem;
#pragma unroll
        for (int r = 0; r < 8; r++) {
            int idx = tid + r * 512;       // 4096 float4 segments total
            int o = idx >> 6;
            int seg = idx & 63;
            int pix = seg * 4;
            int h = h0 + (pix >> 7);
            int w_ = pix & 127;
            const float* s = sD + o * 264 + pix;
            float4 v = make_float4(s[0], s[1], s[2], s[3]);
            *(float4*)(out + ((size_t)b * On + o) * HWn + (size_t)h * Wn + w_) = v;
        }
    }
}

extern "C" void kernel_launch(void* const* d_in, const int* in_sizes, int n_in,
                              void* d_out, int out_size) {
    const float* data   = (const float*)d_in[0];
    const float* offset = (const float*)d_in[1];
    const float* weight = (const float*)d_in[2];
    float* out = (float*)d_out;

    transpose_data_k<<<dim3(HWn / 32, Cn / 32, Bn), dim3(32, 8)>>>(data);
    prep_w_k<<<(KKn * Cn * On + 255) / 256, 256>>>(weight);

    cudaFuncSetAttribute(deform_main_k,
                         cudaFuncAttributeMaxDynamicSharedMemorySize, SMEM_TOTAL);
    deform_main_k<<<dim3(Hn / 2, Bn), 512, SMEM_TOTAL>>>(offset, out);
}

// round 17
// speedup vs baseline: 3.4066x; 1.6698x over previous
#include <cuda_runtime.h>
#include <cuda_fp16.h>

#define Bn 8
#define Cn 64
#define Hn 128
#define Wn 128
#define On 64
#define KKn 9
#define HWn (Hn*Wn)

// Scratch: NHWC fp16 data + fp16 weights [k][c][o].
__device__ __half g_dT[Bn*HWn*Cn];     // 16.8 MB
__device__ __half g_Wh[KKn*Cn*On];     // 72 KB

__device__ __forceinline__ unsigned smem_u32(const void* p) {
    unsigned a;
    asm("{ .reg .u64 t; cvta.to.shared.u64 t, %1; cvt.u32.u64 %0, t; }" : "=r"(a) : "l"(p));
    return a;
}
__device__ __forceinline__ void ldsm_x4(unsigned* r, unsigned addr) {
    asm volatile("ldmatrix.sync.aligned.m8n8.x4.shared.b16 {%0,%1,%2,%3}, [%4];"
        : "=r"(r[0]), "=r"(r[1]), "=r"(r[2]), "=r"(r[3]) : "r"(addr));
}
__device__ __forceinline__ void ldsm_x2t(unsigned* r, unsigned addr) {
    asm volatile("ldmatrix.sync.aligned.m8n8.x2.trans.shared.b16 {%0,%1}, [%2];"
        : "=r"(r[0]), "=r"(r[1]) : "r"(addr));
}
__device__ __forceinline__ void mma_f16(float* d, const unsigned* a, const unsigned* b) {
    asm volatile("mma.sync.aligned.m16n8k16.row.col.f32.f16.f16.f32 "
        "{%0,%1,%2,%3}, {%4,%5,%6,%7}, {%8,%9}, {%0,%1,%2,%3};"
        : "+f"(d[0]), "+f"(d[1]), "+f"(d[2]), "+f"(d[3])
        : "r"(a[0]), "r"(a[1]), "r"(a[2]), "r"(a[3]), "r"(b[0]), "r"(b[1]));
}
#define SWZ(off) ((off) ^ (((off) >> 3) & 0x70))

// ---------------- data transpose: NCHW fp32 -> NHWC fp16 ----------------
__global__ void transpose_data_k(const float* __restrict__ data) {
    __shared__ float tile[32][33];
    int b  = blockIdx.z;
    int c0 = blockIdx.y * 32;
    int p0 = blockIdx.x * 32;
    int tx = threadIdx.x, ty = threadIdx.y;
#pragma unroll
    for (int i = 0; i < 4; i++) {
        int c = c0 + ty + i * 8;
        tile[ty + i * 8][tx] = data[(b * Cn + c) * HWn + p0 + tx];
    }
    __syncthreads();
#pragma unroll
    for (int i = 0; i < 4; i++) {
        int p = p0 + ty + i * 8;
        g_dT[(size_t)(b * HWn + p) * Cn + c0 + tx] = __float2half(tile[tx][ty + i * 8]);
    }
}

// ---------------- weight prep: [o][c][k] fp32 -> fp16 [k][c][o] ----------------
__global__ void prep_w_k(const float* __restrict__ w) {
    int i = blockIdx.x * 256 + threadIdx.x;
    if (i < KKn * Cn * On) {
        int k = i >> 12;                 // i = k*4096 + c*64 + o
        int c = (i >> 6) & 63;
        int o = i & 63;
        g_Wh[i] = __float2half(w[(o * Cn + c) * KKn + k]);
    }
}

// ---------------- main kernel ----------------
// Block = (b, 2 output rows) = 256 pixels, 512 threads, 1 CTA/SM.
// Pipelined: gather(kk) + params(kk+1) + stageW(kk+1) + gemm(kk-1) per barrier.
// A fp16 [256pix][64c] double-buffered (2x32KB), W fp16 [64c][64o] triple (3x8KB),
// params double (2x8KB). Total 106496 B; L1 keeps ~120KB for gather reuse.
// Epilogue reuses smem as float D[64o][264] (67.6KB).
#define SMEM_TOTAL 106496

__global__ void __launch_bounds__(512, 1)
deform_main_k(const float* __restrict__ offset, float* __restrict__ out) {
    extern __shared__ char smem[];
    unsigned sb = smem_u32(smem);
    int tid = threadIdx.x, wid = tid >> 5, lane = tid & 31;
    int b = blockIdx.y, h0 = blockIdx.x * 2;

    const unsigned AB[2] = {0u, 32768u};
    const unsigned WB[3] = {65536u, 73728u, 81920u};
    const unsigned PW[2] = {90112u, 98304u};
    const unsigned PO[2] = {94208u, 102400u};

    const __half* dB = g_dT + (size_t)b * HWn * Cn;

    float acc[8][4];
#pragma unroll
    for (int j = 0; j < 8; j++)
#pragma unroll
        for (int r = 0; r < 4; r++) acc[j][r] = 0.f;

    int g = lane >> 2, tig = lane & 3;
    unsigned aRow = (unsigned)(wid * 16 + (lane & 15)) * 128 + ((lane >> 4) & 1) * 16;
    unsigned bRowLane = (unsigned)(lane & 15) * 128;

    auto params_phase = [&](int kk, int pb) {
        if (tid < 256) {
            int p  = tid;
            int hh = h0 + (p >> 7);
            int ww = p & 127;
            const float* ob = offset + (((size_t)b * 18 + 2 * kk) * Hn + hh) * Wn + ww;
            float oy = ob[0];
            float ox = ob[HWn];
            int ki = kk / 3, kj = kk - ki * 3;
            float py = oy + (float)(hh - 1 + ki);
            float px = ox + (float)(ww - 1 + kj);
            float fy = floorf(py), fx = floorf(px);
            float ly = py - fy, lx = px - fx;
            int y0 = (int)fy, x0 = (int)fx;
            int y1 = y0 + 1, x1 = x0 + 1;
            float vy0 = (y0 >= 0 && y0 < Hn) ? 1.f : 0.f;
            float vy1 = (y1 >= 0 && y1 < Hn) ? 1.f : 0.f;
            float vx0 = (x0 >= 0 && x0 < Wn) ? 1.f : 0.f;
            float vx1 = (x1 >= 0 && x1 < Wn) ? 1.f : 0.f;
            int cy0 = max(0, min(Hn - 1, y0)), cy1 = max(0, min(Hn - 1, y1));
            int cx0 = max(0, min(Wn - 1, x0)), cx1 = max(0, min(Wn - 1, x1));
            float w00 = (1.f - ly) * (1.f - lx) * vy0 * vx0;
            float w01 = (1.f - ly) * lx         * vy0 * vx1;
            float w10 = ly         * (1.f - lx) * vy1 * vx0;
            float w11 = ly         * lx         * vy1 * vx1;
            ((int4*)(smem + PO[pb]))[p] =
                make_int4((cy0 * Wn + cx0) * Cn, (cy0 * Wn + cx1) * Cn,
                          (cy1 * Wn + cx0) * Cn, (cy1 * Wn + cx1) * Cn);
            ((float4*)(smem + PW[pb]))[p] = make_float4(w00, w01, w10, w11);
        }
    };
    auto stage_w = [&](int kk, int wb) {
        const uint4* src = (const uint4*)((const char*)g_Wh + kk * 8192);
        unsigned sw = SWZ((unsigned)(tid * 16));
        *(uint4*)(smem + WB[wb] + sw) = src[tid];
    };
    auto gather_phase = [&](int ab, int pb) {
        int cg = tid & 7;        // channel group: c = 8cg..8cg+7
        int pl = tid >> 3;       // 0..63
        const __half* dC = dB + cg * 8;
        const int4*   of = (const int4*)(smem + PO[pb]);
        const float4* wt = (const float4*)(smem + PW[pb]);
#pragma unroll
        for (int it = 0; it < 4; it++) {
            int p = pl + it * 64;
            int4   a  = of[p];
            float4 wv = wt[p];
            uint4 q00 = *(const uint4*)(dC + a.x);
            uint4 q01 = *(const uint4*)(dC + a.y);
            uint4 q10 = *(const uint4*)(dC + a.z);
            uint4 q11 = *(const uint4*)(dC + a.w);
            const __half2* h00 = (const __half2*)&q00;
            const __half2* h01 = (const __half2*)&q01;
            const __half2* h10 = (const __half2*)&q10;
            const __half2* h11 = (const __half2*)&q11;
            uint4 sOut;
            __half2* so = (__half2*)&sOut;
#pragma unroll
            for (int i = 0; i < 4; i++) {
                float2 f00 = __half22float2(h00[i]);
                float2 f01 = __half22float2(h01[i]);
                float2 f10 = __half22float2(h10[i]);
                float2 f11 = __half22float2(h11[i]);
                float2 r;
                r.x = wv.x * f00.x + wv.y * f01.x + wv.z * f10.x + wv.w * f11.x;
                r.y = wv.x * f00.y + wv.y * f01.y + wv.z * f10.y + wv.w * f11.y;
                so[i] = __float22half2_rn(r);
            }
            unsigned sw = SWZ((unsigned)(p * 128 + cg * 16));
            *(uint4*)(smem + AB[ab] + sw) = sOut;
        }
    };
    auto gemm_phase = [&](int ab, int wb) {
        unsigned af[4], bf[8][2];
#pragma unroll
        for (int ks = 0; ks < 4; ks++) {
#pragma unroll
            for (int j = 0; j < 8; j++)
                ldsm_x2t(bf[j], sb + WB[wb] + SWZ(bRowLane + ks * 2048 + j * 16));
            ldsm_x4(af, sb + AB[ab] + SWZ(aRow + ks * 32));
#pragma unroll
            for (int j = 0; j < 8; j++) mma_f16(acc[j], af, bf[j]);
        }
    };

    // ---- prologue ----
    params_phase(0, 0);
    stage_w(0, 0);
    __syncthreads();

    // ---- pipelined main loop ----
#pragma unroll 1
    for (int kk = 0; kk < KKn; kk++) {
        int cb = kk & 1;
        gather_phase(cb, cb);
        if (kk + 1 < KKn) {
            params_phase(kk + 1, cb ^ 1);
            stage_w(kk + 1, (kk + 1) % 3);
        }
        if (kk > 0)
            gemm_phase((kk - 1) & 1, (kk - 1) % 3);
        __syncthreads();
    }
    gemm_phase((KKn - 1) & 1, (KKn - 1) % 3);

    // ---- epilogue: fragments -> smem [64o][264] -> coalesced stores ----
    __syncthreads();
    {
        float* sD = (float*)smem;
        int pixA = wid * 16 + g;
        int pixB = pixA + 8;
#pragma unroll
        for (int j = 0; j < 8; j++) {
            int o = j * 8 + tig * 2;
            sD[o * 264 + pixA]       = acc[j][0];
            sD[(o + 1) * 264 + pixA] = acc[j][1];
            sD[o * 264 + pixB]       = acc[j][2];
            sD[(o + 1) * 264 + pixB] = acc[j][3];
        }
    }
    __syncthreads();
    {
        const float* sD = (const float*)smem;
#pragma unroll
        for (int r = 0; r < 8; r++) {
            int idx = tid + r * 512;
            int o = idx >> 6;
            int seg = idx & 63;
            int pix = seg * 4;
            int h = h0 + (pix >> 7);
            int w_ = pix & 127;
            const float* s = sD + o * 264 + pix;
            float4 v = make_float4(s[0], s[1], s[2], s[3]);
            *(float4*)(out + ((size_t)b * On + o) * HWn + (size_t)h * Wn + w_) = v;
        }
    }
}

extern "C" void kernel_launch(void* const* d_in, const int* in_sizes, int n_in,
                              void* d_out, int out_size) {
    const float* data   = (const float*)d_in[0];
    const float* offset = (const float*)d_in[1];
    const float* weight = (const float*)d_in[2];
    float* out = (float*)d_out;

    transpose_data_k<<<dim3(HWn / 32, Cn / 32, Bn), dim3(32, 8)>>>(data);
    prep_w_k<<<(KKn * Cn * On + 255) / 256, 256>>>(weight);

    cudaFuncSetAttribute(deform_main_k,
                         cudaFuncAttributeMaxDynamicSharedMemorySize, SMEM_TOTAL);
    deform_main_k<<<dim3(Hn / 2, Bn), 512, SMEM_TOTAL>>>(offset, out);
}